// round 1
// baseline (speedup 1.0000x reference)
#include <cuda_runtime.h>
#include <math.h>

#define Bdim 4
#define Tdim 512
#define Hdim 32
#define Ndim 64
#define Ddim 2048           // Hdim*Ndim
#define Mtot (Bdim*Tdim)    // 2048
#define Ktot Ddim           // 2048

// scratch for scan output y [B,T,D]  (16 MB) — __device__ global (no allocs allowed)
__device__ float g_y[Bdim * Tdim * Ddim];

// ---------------------------------------------------------------------------
// Kernel 1: RWKV-7 WKV scan. One block per (b,h); thread i owns state row i
// (64 fp32 registers). All per-step vectors live in shared; reads are
// broadcast (conflict-free) float4 loads.
// ---------------------------------------------------------------------------
__global__ void __launch_bounds__(Ndim) wkv7_scan_kernel(
    const float* __restrict__ r, const float* __restrict__ w,
    const float* __restrict__ k, const float* __restrict__ v,
    const float* __restrict__ iclr)
{
    const int bh = blockIdx.x;          // 0..B*H-1
    const int b  = bh >> 5;             // /H (H=32)
    const int h  = bh & 31;
    const int i  = threadIdx.x;         // 0..63
    const int lane = i & 31, warp = i >> 5;

    __shared__ __align__(16) float s_r[Ndim], s_d[Ndim], s_k[Ndim],
                                   s_kk[Ndim], s_b[Ndim];
    __shared__ float s_red[2];

    float state[Ndim];
#pragma unroll
    for (int j = 0; j < Ndim; j++) state[j] = 0.f;

    // element index for (b, t, h, i); t stride = H*N
    size_t idx = (((size_t)b * Tdim) * Hdim + h) * Ndim + i;
    const size_t tstep = (size_t)Hdim * Ndim;
    size_t yidx = ((size_t)b * Tdim) * Ddim + h * Ndim + i;

    for (int t = 0; t < Tdim; t++, idx += tstep, yidx += Ddim) {
        const float r_i = r[idx];
        const float w_i = w[idx];
        const float k_i = k[idx];
        const float v_i = v[idx];
        const float c_i = iclr[idx];

        const float d_i = __expf(-__expf(w_i));   // decay in (0,1)

        // block-wide sum of k^2 (two warps)
        float p = k_i * k_i;
#pragma unroll
        for (int o = 16; o; o >>= 1) p += __shfl_xor_sync(0xffffffffu, p, o);
        if (lane == 0) s_red[warp] = p;

        s_r[i] = r_i; s_d[i] = d_i; s_k[i] = k_i;
        __syncthreads();

        const float ksum = s_red[0] + s_red[1];
        const float kk_i = k_i * rsqrtf(ksum + 1e-12f);
        const float sig  = 1.0f / (1.0f + __expf(-c_i));
        s_kk[i] = kk_i;
        s_b[i]  = kk_i * sig;
        __syncthreads();

        // sa = -dot(state_row, kk)
        float a0 = 0.f, a1 = 0.f, a2 = 0.f, a3 = 0.f;
        const float4* kk4 = (const float4*)s_kk;
#pragma unroll
        for (int j4 = 0; j4 < Ndim / 4; j4++) {
            float4 q = kk4[j4];
            a0 = fmaf(state[4*j4+0], q.x, a0);
            a1 = fmaf(state[4*j4+1], q.y, a1);
            a2 = fmaf(state[4*j4+2], q.z, a2);
            a3 = fmaf(state[4*j4+3], q.w, a3);
        }
        const float sa = -((a0 + a1) + (a2 + a3));

        // state = state*d + sa*b + v_i*k ;  y = dot(state, r)
        float y0 = 0.f, y1 = 0.f, y2 = 0.f, y3 = 0.f;
        const float4* r4 = (const float4*)s_r;
        const float4* d4 = (const float4*)s_d;
        const float4* k4 = (const float4*)s_k;
        const float4* b4 = (const float4*)s_b;
#pragma unroll
        for (int j4 = 0; j4 < Ndim / 4; j4++) {
            float4 dd = d4[j4], bb = b4[j4], kq = k4[j4], rr = r4[j4];
            float t0, t1, t2, t3;
            t0 = fmaf(sa, bb.x, v_i * kq.x);
            t1 = fmaf(sa, bb.y, v_i * kq.y);
            t2 = fmaf(sa, bb.z, v_i * kq.z);
            t3 = fmaf(sa, bb.w, v_i * kq.w);
            state[4*j4+0] = fmaf(state[4*j4+0], dd.x, t0);
            state[4*j4+1] = fmaf(state[4*j4+1], dd.y, t1);
            state[4*j4+2] = fmaf(state[4*j4+2], dd.z, t2);
            state[4*j4+3] = fmaf(state[4*j4+3], dd.w, t3);
            y0 = fmaf(state[4*j4+0], rr.x, y0);
            y1 = fmaf(state[4*j4+1], rr.y, y1);
            y2 = fmaf(state[4*j4+2], rr.z, y2);
            y3 = fmaf(state[4*j4+3], rr.w, y3);
        }
        g_y[yidx] = (y0 + y1) + (y2 + y3);
        __syncthreads();   // protect shared before next t's writes
    }
}

// ---------------------------------------------------------------------------
// Kernel 2: out[m, o] = scale[o] * sum_d y[m,d] * Wq[o,d]
// A = y [M=2048, K=2048] row-major; Bq = Wq [N=2048, K=2048] row-major (NT GEMM)
// fp32 SIMT tiled: 64x64 block tile, BK=16, 256 threads, 4x4 micro-tile.
// int->float dequant happens at the shared-memory store.
// ---------------------------------------------------------------------------
#define BM 64
#define BN 64
#define BK 16

__global__ void __launch_bounds__(256) dequant_gemm_kernel(
    const int* __restrict__ Wq, const float* __restrict__ scale,
    float* __restrict__ out)
{
    __shared__ __align__(16) float As[BK][BM + 4];
    __shared__ __align__(16) float Bs[BK][BN + 4];

    const int tid = threadIdx.x;
    const int bm  = blockIdx.y * BM;
    const int bn  = blockIdx.x * BN;

    // load indices: lk = k-in-tile (contiguous across threads -> coalesced)
    const int lk = tid & 15;       // 0..15
    const int lr = tid >> 4;       // 0..15 (row group; 4 rows each)

    // compute indices: 16x16 thread grid, 4x4 micro-tiles
    const int tx = tid & 15;       // n direction
    const int ty = tid >> 4;       // m direction

    float acc[4][4];
#pragma unroll
    for (int a = 0; a < 4; a++)
#pragma unroll
        for (int bb = 0; bb < 4; bb++) acc[a][bb] = 0.f;

    const float* A = g_y;

    for (int k0 = 0; k0 < Ktot; k0 += BK) {
#pragma unroll
        for (int ii = 0; ii < 4; ii++) {
            int m = lr + ii * 16;
            As[lk][m] = A[(size_t)(bm + m) * Ktot + k0 + lk];
            int n = lr + ii * 16;
            Bs[lk][n] = (float)Wq[(size_t)(bn + n) * Ktot + k0 + lk];
        }
        __syncthreads();

#pragma unroll
        for (int kk = 0; kk < BK; kk++) {
            float4 av = *(const float4*)&As[kk][ty * 4];
            float4 bv = *(const float4*)&Bs[kk][tx * 4];
            const float ar[4] = {av.x, av.y, av.z, av.w};
            const float br[4] = {bv.x, bv.y, bv.z, bv.w};
#pragma unroll
            for (int a = 0; a < 4; a++)
#pragma unroll
                for (int bb = 0; bb < 4; bb++)
                    acc[a][bb] = fmaf(ar[a], br[bb], acc[a][bb]);
        }
        __syncthreads();
    }

    // epilogue: per-output-row (o = n) scale
    float sc[4];
#pragma unroll
    for (int bb = 0; bb < 4; bb++) sc[bb] = scale[bn + tx * 4 + bb];

#pragma unroll
    for (int a = 0; a < 4; a++) {
        const size_t row = (size_t)(bm + ty * 4 + a) * Ddim;
#pragma unroll
        for (int bb = 0; bb < 4; bb++)
            out[row + bn + tx * 4 + bb] = acc[a][bb] * sc[bb];
    }
}

// ---------------------------------------------------------------------------
extern "C" void kernel_launch(void* const* d_in, const int* in_sizes, int n_in,
                              void* d_out, int out_size)
{
    const float* r     = (const float*)d_in[0];
    const float* w     = (const float*)d_in[1];
    const float* k     = (const float*)d_in[2];
    const float* v     = (const float*)d_in[3];
    const float* iclr  = (const float*)d_in[4];
    const int*   wq    = (const int*)d_in[5];
    const float* wsc   = (const float*)d_in[6];
    float* out = (float*)d_out;

    wkv7_scan_kernel<<<Bdim * Hdim, Ndim>>>(r, w, k, v, iclr);

    dim3 grid(Ddim / BN, Mtot / BM);
    dequant_gemm_kernel<<<grid, 256>>>(wq, wsc, out);
}

// round 2
// speedup vs baseline: 1.2751x; 1.2751x over previous
#include <cuda_runtime.h>
#include <math.h>

#define Bdim 4
#define Tdim 512
#define Hdim 32
#define Ndim 64
#define Ddim 2048           // Hdim*Ndim
#define Mtot (Bdim*Tdim)    // 2048
#define Ktot Ddim           // 2048

// scratch for scan output y [B,T,D]  (16 MB)
__device__ float g_y[Bdim * Tdim * Ddim];

// ---------------------------------------------------------------------------
// Kernel 1: RWKV-7 WKV scan.
// One block (256 threads) per (b,h). Thread layout: row = tid>>2 (state row,
// 0..63), seg = tid&3 (16-column segment). Each thread holds 16 fp32 state
// registers. Dot products reduce across the 4-lane quad via shfl.
// Scalar per-channel work done by tid<64 in a 2-phase shared handoff.
// ---------------------------------------------------------------------------
__global__ void __launch_bounds__(256) wkv7_scan_kernel(
    const float* __restrict__ r, const float* __restrict__ w,
    const float* __restrict__ k, const float* __restrict__ v,
    const float* __restrict__ iclr)
{
    const int bh = blockIdx.x;          // 0..127
    const int b  = bh >> 5;
    const int h  = bh & 31;
    const int tid = threadIdx.x;
    const int row = tid >> 2;           // 0..63
    const int seg = tid & 3;            // 0..3
    const int jb  = seg * 16;           // column base

    __shared__ __align__(16) float s_r[Ndim], s_d[Ndim], s_k[Ndim],
                                   s_kk[Ndim], s_b[Ndim], s_v[Ndim];
    __shared__ float s_red[2];

    float state[16];
#pragma unroll
    for (int c = 0; c < 16; c++) state[c] = 0.f;

    // scalar-phase channel (valid for tid<64)
    size_t idx = (((size_t)b * Tdim) * Hdim + h) * Ndim + tid;
    const size_t tstep = (size_t)Hdim * Ndim;
    // y output base for this thread's row
    size_t ybase = ((size_t)b * Tdim) * Ddim + h * Ndim + row;

    float r_i = 0.f, w_i = 0.f, k_i = 0.f, v_i = 0.f, c_i = 0.f;
    if (tid < 64) {
        r_i = __ldg(r + idx); w_i = __ldg(w + idx); k_i = __ldg(k + idx);
        v_i = __ldg(v + idx); c_i = __ldg(iclr + idx);
    }

    for (int t = 0; t < Tdim; t++) {
        float sig = 0.f, kcur = 0.f;
        if (tid < 64) {
            const float d_i = __expf(-__expf(w_i));
            sig  = 1.0f / (1.0f + __expf(-c_i));
            kcur = k_i;
            float p = k_i * k_i;
#pragma unroll
            for (int o = 16; o; o >>= 1) p += __shfl_xor_sync(0xffffffffu, p, o);
            if ((tid & 31) == 0) s_red[tid >> 5] = p;
            s_r[tid] = r_i; s_d[tid] = d_i; s_k[tid] = k_i; s_v[tid] = v_i;
        }
        __syncthreads();

        if (tid < 64) {
            const float ksum = s_red[0] + s_red[1];
            const float kk_i = kcur * rsqrtf(ksum + 1e-12f);
            s_kk[tid] = kk_i;
            s_b[tid]  = kk_i * sig;
            // prefetch next step's inputs while everyone computes
            if (t + 1 < Tdim) {
                idx += tstep;
                r_i = __ldg(r + idx); w_i = __ldg(w + idx); k_i = __ldg(k + idx);
                v_i = __ldg(v + idx); c_i = __ldg(iclr + idx);
            }
        }
        __syncthreads();

        // --- compute phase (all 256 threads) ---
        // sa partial: dot(state_seg, kk_seg)
        const float4* kk4 = (const float4*)(s_kk + jb);
        float p0 = 0.f, p1 = 0.f, p2 = 0.f, p3 = 0.f;
#pragma unroll
        for (int q = 0; q < 4; q++) {
            float4 kv = kk4[q];
            p0 = fmaf(state[4*q+0], kv.x, p0);
            p1 = fmaf(state[4*q+1], kv.y, p1);
            p2 = fmaf(state[4*q+2], kv.z, p2);
            p3 = fmaf(state[4*q+3], kv.w, p3);
        }
        float sa_p = (p0 + p1) + (p2 + p3);
        sa_p += __shfl_xor_sync(0xffffffffu, sa_p, 1);
        sa_p += __shfl_xor_sync(0xffffffffu, sa_p, 2);
        const float sa = -sa_p;
        const float vv = s_v[row];

        const float4* d4 = (const float4*)(s_d  + jb);
        const float4* b4 = (const float4*)(s_b  + jb);
        const float4* k4 = (const float4*)(s_k  + jb);
        const float4* r4 = (const float4*)(s_r  + jb);
        float y0 = 0.f, y1 = 0.f, y2 = 0.f, y3 = 0.f;
#pragma unroll
        for (int q = 0; q < 4; q++) {
            float4 dd = d4[q], bb = b4[q], kq = k4[q], rr = r4[q];
            float t0 = fmaf(sa, bb.x, vv * kq.x);
            float t1 = fmaf(sa, bb.y, vv * kq.y);
            float t2 = fmaf(sa, bb.z, vv * kq.z);
            float t3 = fmaf(sa, bb.w, vv * kq.w);
            state[4*q+0] = fmaf(state[4*q+0], dd.x, t0);
            state[4*q+1] = fmaf(state[4*q+1], dd.y, t1);
            state[4*q+2] = fmaf(state[4*q+2], dd.z, t2);
            state[4*q+3] = fmaf(state[4*q+3], dd.w, t3);
            y0 = fmaf(state[4*q+0], rr.x, y0);
            y1 = fmaf(state[4*q+1], rr.y, y1);
            y2 = fmaf(state[4*q+2], rr.z, y2);
            y3 = fmaf(state[4*q+3], rr.w, y3);
        }
        float yp = (y0 + y1) + (y2 + y3);
        yp += __shfl_xor_sync(0xffffffffu, yp, 1);
        yp += __shfl_xor_sync(0xffffffffu, yp, 2);
        if (seg == 0) g_y[ybase + (size_t)t * Ddim] = yp;
        __syncthreads();
    }
}

// ---------------------------------------------------------------------------
// Kernel 2: out[m, o] = scale[o] * sum_d y[m,d] * Wq[o,d]   (NT GEMM)
// 128x128x16 block tile, 256 threads, 8x8 micro-tile, register-prefetched
// global loads, conflict-free STS (lanes span m-dim).
// ---------------------------------------------------------------------------
#define GBM 128
#define GBN 128
#define GBK 16

__global__ void __launch_bounds__(256) dequant_gemm_kernel(
    const int* __restrict__ Wq, const float* __restrict__ scale,
    float* __restrict__ out)
{
    __shared__ __align__(16) float As[GBK][GBM];
    __shared__ __align__(16) float Bs[GBK][GBN];

    const int tid = threadIdx.x;
    const int bm  = blockIdx.y * GBM;
    const int bn  = blockIdx.x * GBN;

    // load mapping: lm = row within tile (lanes consecutive -> STS conflict-free)
    const int lm  = tid & 63;             // 0..63 (also +64 for 2nd row)
    const int lk4 = (tid >> 6) * 4;       // 0,4,8,12 (float4 k-offset)

    // compute mapping: 16x16 thread grid, 8x8 micro-tile
    const int tx = tid & 15;              // n
    const int ty = tid >> 4;              // m

    const float* __restrict__ A = g_y;

    float acc[8][8];
#pragma unroll
    for (int a = 0; a < 8; a++)
#pragma unroll
        for (int c = 0; c < 8; c++) acc[a][c] = 0.f;

    // prefetch first tile into regs
    float4 pa0 = *(const float4*)&A [(size_t)(bm + lm)      * Ktot + lk4];
    float4 pa1 = *(const float4*)&A [(size_t)(bm + lm + 64) * Ktot + lk4];
    int4   pb0 = *(const int4*)  &Wq[(size_t)(bn + lm)      * Ktot + lk4];
    int4   pb1 = *(const int4*)  &Wq[(size_t)(bn + lm + 64) * Ktot + lk4];

    for (int k0 = 0; k0 < Ktot; k0 += GBK) {
        // commit prefetched tile to shared (transposed)
        As[lk4+0][lm]      = pa0.x; As[lk4+1][lm]      = pa0.y;
        As[lk4+2][lm]      = pa0.z; As[lk4+3][lm]      = pa0.w;
        As[lk4+0][lm+64]   = pa1.x; As[lk4+1][lm+64]   = pa1.y;
        As[lk4+2][lm+64]   = pa1.z; As[lk4+3][lm+64]   = pa1.w;
        Bs[lk4+0][lm]      = (float)pb0.x; Bs[lk4+1][lm]      = (float)pb0.y;
        Bs[lk4+2][lm]      = (float)pb0.z; Bs[lk4+3][lm]      = (float)pb0.w;
        Bs[lk4+0][lm+64]   = (float)pb1.x; Bs[lk4+1][lm+64]   = (float)pb1.y;
        Bs[lk4+2][lm+64]   = (float)pb1.z; Bs[lk4+3][lm+64]   = (float)pb1.w;
        __syncthreads();

        if (k0 + GBK < Ktot) {
            const int kn = k0 + GBK;
            pa0 = *(const float4*)&A [(size_t)(bm + lm)      * Ktot + kn + lk4];
            pa1 = *(const float4*)&A [(size_t)(bm + lm + 64) * Ktot + kn + lk4];
            pb0 = *(const int4*)  &Wq[(size_t)(bn + lm)      * Ktot + kn + lk4];
            pb1 = *(const int4*)  &Wq[(size_t)(bn + lm + 64) * Ktot + kn + lk4];
        }

#pragma unroll
        for (int kk = 0; kk < GBK; kk++) {
            float4 alo = *(const float4*)&As[kk][ty * 8];
            float4 ahi = *(const float4*)&As[kk][ty * 8 + 4];
            float4 blo = *(const float4*)&Bs[kk][tx * 8];
            float4 bhi = *(const float4*)&Bs[kk][tx * 8 + 4];
            const float ar[8] = {alo.x, alo.y, alo.z, alo.w,
                                 ahi.x, ahi.y, ahi.z, ahi.w};
            const float br[8] = {blo.x, blo.y, blo.z, blo.w,
                                 bhi.x, bhi.y, bhi.z, bhi.w};
#pragma unroll
            for (int a = 0; a < 8; a++)
#pragma unroll
                for (int c = 0; c < 8; c++)
                    acc[a][c] = fmaf(ar[a], br[c], acc[a][c]);
        }
        __syncthreads();
    }

    // epilogue: per-output-column scale (o = n index), vectorized stores
    float4 sc_lo = *(const float4*)&scale[bn + tx * 8];
    float4 sc_hi = *(const float4*)&scale[bn + tx * 8 + 4];
    const float sc[8] = {sc_lo.x, sc_lo.y, sc_lo.z, sc_lo.w,
                         sc_hi.x, sc_hi.y, sc_hi.z, sc_hi.w};

#pragma unroll
    for (int a = 0; a < 8; a++) {
        const size_t rowoff = (size_t)(bm + ty * 8 + a) * Ddim + bn + tx * 8;
        float4 o0, o1;
        o0.x = acc[a][0] * sc[0]; o0.y = acc[a][1] * sc[1];
        o0.z = acc[a][2] * sc[2]; o0.w = acc[a][3] * sc[3];
        o1.x = acc[a][4] * sc[4]; o1.y = acc[a][5] * sc[5];
        o1.z = acc[a][6] * sc[6]; o1.w = acc[a][7] * sc[7];
        *(float4*)&out[rowoff]     = o0;
        *(float4*)&out[rowoff + 4] = o1;
    }
}

// ---------------------------------------------------------------------------
extern "C" void kernel_launch(void* const* d_in, const int* in_sizes, int n_in,
                              void* d_out, int out_size)
{
    const float* r     = (const float*)d_in[0];
    const float* w     = (const float*)d_in[1];
    const float* k     = (const float*)d_in[2];
    const float* v     = (const float*)d_in[3];
    const float* iclr  = (const float*)d_in[4];
    const int*   wq    = (const int*)d_in[5];
    const float* wsc   = (const float*)d_in[6];
    float* out = (float*)d_out;

    wkv7_scan_kernel<<<Bdim * Hdim, 256>>>(r, w, k, v, iclr);

    dim3 grid(Ddim / GBN, Mtot / GBM);
    dequant_gemm_kernel<<<grid, 256>>>(wq, wsc, out);
}

// round 3
// speedup vs baseline: 1.4209x; 1.1143x over previous
#include <cuda_runtime.h>
#include <math.h>

#define Bdim 4
#define Tdim 512
#define Hdim 32
#define Ndim 64
#define Ddim 2048           // Hdim*Ndim
#define Mtot (Bdim*Tdim)    // 2048
#define Ktot Ddim           // 2048

// device scratch (no allocs allowed)
__device__ float g_y [Bdim * Tdim * Ddim];   // scan output y [B,T,D]
__device__ float g_d [Bdim * Tdim * Ddim];   // decay
__device__ float g_kk[Bdim * Tdim * Ddim];   // normalized k
__device__ float g_bb[Bdim * Tdim * Ddim];   // kk * sigmoid(iclr)

// ---------------------------------------------------------------------------
// Kernel 0: elementwise precompute. One warp per (b,t,h) vector of 64;
// lane handles elements lane and lane+32.
// ---------------------------------------------------------------------------
__global__ void __launch_bounds__(256) wkv7_pre_kernel(
    const float* __restrict__ w, const float* __restrict__ k,
    const float* __restrict__ iclr)
{
    const int vec  = blockIdx.x * 8 + (threadIdx.x >> 5);   // 0..B*T*H-1
    const int lane = threadIdx.x & 31;
    const size_t base = (size_t)vec * Ndim;

    float k0 = k[base + lane], k1 = k[base + lane + 32];
    float p = fmaf(k0, k0, k1 * k1);
#pragma unroll
    for (int o = 16; o; o >>= 1) p += __shfl_xor_sync(0xffffffffu, p, o);
    const float inv = rsqrtf(p + 1e-12f);

    float w0 = w[base + lane], w1 = w[base + lane + 32];
    float c0 = iclr[base + lane], c1 = iclr[base + lane + 32];

    g_d[base + lane]      = __expf(-__expf(w0));
    g_d[base + lane + 32] = __expf(-__expf(w1));
    const float kk0 = k0 * inv, kk1 = k1 * inv;
    g_kk[base + lane]      = kk0;
    g_kk[base + lane + 32] = kk1;
    g_bb[base + lane]      = kk0 / (1.0f + __expf(-c0));
    g_bb[base + lane + 32] = kk1 / (1.0f + __expf(-c1));
}

// ---------------------------------------------------------------------------
// Kernel 1: WKV scan, streaming form. One block (256 thr) per (b,h).
// row = tid>>2 owns state row, seg = tid&3 owns a 16-col segment.
// Per-step vectors (d,kk,b,k,r,v) staged in double-buffered shared via
// 96 loader threads with prefetch distance 2; ONE __syncthreads per step.
// ---------------------------------------------------------------------------
__global__ void __launch_bounds__(256) wkv7_scan_kernel(
    const float* __restrict__ r, const float* __restrict__ k,
    const float* __restrict__ v)
{
    const int bh = blockIdx.x;          // 0..127
    const int b  = bh >> 5;
    const int h  = bh & 31;
    const int tid = threadIdx.x;
    const int row = tid >> 2;           // 0..63
    const int seg = tid & 3;            // 0..3
    const int jb  = seg * 16;

    // layout (floats): d[0,64) kk[64,128) b[128,192) k[192,256) r[256,320) v[320,384)
    __shared__ __align__(16) float sbuf[2][6 * Ndim];

    float state[16];
#pragma unroll
    for (int c = 0; c < 16; c++) state[c] = 0.f;

    // loader setup: tid<96 loads float4 #tid of the 6-vector group each step
    const float* __restrict__ srcs[6];
    srcs[0] = g_d; srcs[1] = g_kk; srcs[2] = g_bb;
    srcs[3] = k;   srcs[4] = r;    srcs[5] = v;
    const int lvec = tid >> 4;          // 0..5
    const int lq   = tid & 15;          // 0..15
    const size_t vstep = (size_t)Hdim * Ndim / 4;   // float4 stride per t
    const float4* gptr = nullptr;
    float4 regA, regB;
    if (tid < 96) {
        gptr = (const float4*)srcs[lvec]
             + (((size_t)b * Tdim) * Hdim + h) * (Ndim / 4) + lq;
        regA = *gptr; gptr += vstep;          // t = 0
        regB = *gptr; gptr += vstep;          // t = 1
        ((float4*)sbuf[0])[tid] = regA;       // commit t=0
    }
    __syncthreads();

    size_t ybase = ((size_t)b * Tdim) * Ddim + h * Ndim + row;

    for (int t = 0; t < Tdim; t++) {
        // stage t+1 into other buffer; issue load for t+2
        if (tid < 96) {
            ((float4*)sbuf[(t + 1) & 1])[tid] = regB;
            if (t + 2 < Tdim) { regB = *gptr; }
            gptr += vstep;
        }

        const float* s = sbuf[t & 1];
        const float4* d4  = (const float4*)(s +   0 + jb);
        const float4* kk4 = (const float4*)(s +  64 + jb);
        const float4* b4  = (const float4*)(s + 128 + jb);
        const float4* k4  = (const float4*)(s + 192 + jb);
        const float4* r4  = (const float4*)(s + 256 + jb);
        const float vv = s[320 + row];

        // sa = -dot(state, kk)  (quad-partial + 2 shfl)
        float p0 = 0.f, p1 = 0.f, p2 = 0.f, p3 = 0.f;
#pragma unroll
        for (int q = 0; q < 4; q++) {
            float4 kv = kk4[q];
            p0 = fmaf(state[4*q+0], kv.x, p0);
            p1 = fmaf(state[4*q+1], kv.y, p1);
            p2 = fmaf(state[4*q+2], kv.z, p2);
            p3 = fmaf(state[4*q+3], kv.w, p3);
        }
        float sa_p = (p0 + p1) + (p2 + p3);
        sa_p += __shfl_xor_sync(0xffffffffu, sa_p, 1);
        sa_p += __shfl_xor_sync(0xffffffffu, sa_p, 2);
        const float sa = -sa_p;

        // state = state*d + sa*b + v*k ; y = dot(state, r)
        float y0 = 0.f, y1 = 0.f, y2 = 0.f, y3 = 0.f;
#pragma unroll
        for (int q = 0; q < 4; q++) {
            float4 dd = d4[q], bb = b4[q], kq = k4[q], rr = r4[q];
            float t0 = fmaf(sa, bb.x, vv * kq.x);
            float t1 = fmaf(sa, bb.y, vv * kq.y);
            float t2 = fmaf(sa, bb.z, vv * kq.z);
            float t3 = fmaf(sa, bb.w, vv * kq.w);
            state[4*q+0] = fmaf(state[4*q+0], dd.x, t0);
            state[4*q+1] = fmaf(state[4*q+1], dd.y, t1);
            state[4*q+2] = fmaf(state[4*q+2], dd.z, t2);
            state[4*q+3] = fmaf(state[4*q+3], dd.w, t3);
            y0 = fmaf(state[4*q+0], rr.x, y0);
            y1 = fmaf(state[4*q+1], rr.y, y1);
            y2 = fmaf(state[4*q+2], rr.z, y2);
            y3 = fmaf(state[4*q+3], rr.w, y3);
        }
        float yp = (y0 + y1) + (y2 + y3);
        yp += __shfl_xor_sync(0xffffffffu, yp, 1);
        yp += __shfl_xor_sync(0xffffffffu, yp, 2);
        if (seg == 0) g_y[ybase + (size_t)t * Ddim] = yp;

        __syncthreads();
    }
}

// ---------------------------------------------------------------------------
// Kernel 2: out[m, o] = scale[o] * sum_d y[m,d] * Wq[o,d]   (NT GEMM)
// 128x128x16 block tile, 256 threads, 8x8 micro-tile. (unchanged from R1)
// ---------------------------------------------------------------------------
#define GBM 128
#define GBN 128
#define GBK 16

__global__ void __launch_bounds__(256) dequant_gemm_kernel(
    const int* __restrict__ Wq, const float* __restrict__ scale,
    float* __restrict__ out)
{
    __shared__ __align__(16) float As[GBK][GBM];
    __shared__ __align__(16) float Bs[GBK][GBN];

    const int tid = threadIdx.x;
    const int bm  = blockIdx.y * GBM;
    const int bn  = blockIdx.x * GBN;

    const int lm  = tid & 63;
    const int lk4 = (tid >> 6) * 4;

    const int tx = tid & 15;
    const int ty = tid >> 4;

    const float* __restrict__ A = g_y;

    float acc[8][8];
#pragma unroll
    for (int a = 0; a < 8; a++)
#pragma unroll
        for (int c = 0; c < 8; c++) acc[a][c] = 0.f;

    float4 pa0 = *(const float4*)&A [(size_t)(bm + lm)      * Ktot + lk4];
    float4 pa1 = *(const float4*)&A [(size_t)(bm + lm + 64) * Ktot + lk4];
    int4   pb0 = *(const int4*)  &Wq[(size_t)(bn + lm)      * Ktot + lk4];
    int4   pb1 = *(const int4*)  &Wq[(size_t)(bn + lm + 64) * Ktot + lk4];

    for (int k0 = 0; k0 < Ktot; k0 += GBK) {
        As[lk4+0][lm]      = pa0.x; As[lk4+1][lm]      = pa0.y;
        As[lk4+2][lm]      = pa0.z; As[lk4+3][lm]      = pa0.w;
        As[lk4+0][lm+64]   = pa1.x; As[lk4+1][lm+64]   = pa1.y;
        As[lk4+2][lm+64]   = pa1.z; As[lk4+3][lm+64]   = pa1.w;
        Bs[lk4+0][lm]      = (float)pb0.x; Bs[lk4+1][lm]      = (float)pb0.y;
        Bs[lk4+2][lm]      = (float)pb0.z; Bs[lk4+3][lm]      = (float)pb0.w;
        Bs[lk4+0][lm+64]   = (float)pb1.x; Bs[lk4+1][lm+64]   = (float)pb1.y;
        Bs[lk4+2][lm+64]   = (float)pb1.z; Bs[lk4+3][lm+64]   = (float)pb1.w;
        __syncthreads();

        if (k0 + GBK < Ktot) {
            const int kn = k0 + GBK;
            pa0 = *(const float4*)&A [(size_t)(bm + lm)      * Ktot + kn + lk4];
            pa1 = *(const float4*)&A [(size_t)(bm + lm + 64) * Ktot + kn + lk4];
            pb0 = *(const int4*)  &Wq[(size_t)(bn + lm)      * Ktot + kn + lk4];
            pb1 = *(const int4*)  &Wq[(size_t)(bn + lm + 64) * Ktot + kn + lk4];
        }

#pragma unroll
        for (int kk = 0; kk < GBK; kk++) {
            float4 alo = *(const float4*)&As[kk][ty * 8];
            float4 ahi = *(const float4*)&As[kk][ty * 8 + 4];
            float4 blo = *(const float4*)&Bs[kk][tx * 8];
            float4 bhi = *(const float4*)&Bs[kk][tx * 8 + 4];
            const float ar[8] = {alo.x, alo.y, alo.z, alo.w,
                                 ahi.x, ahi.y, ahi.z, ahi.w};
            const float br[8] = {blo.x, blo.y, blo.z, blo.w,
                                 bhi.x, bhi.y, bhi.z, bhi.w};
#pragma unroll
            for (int a = 0; a < 8; a++)
#pragma unroll
                for (int c = 0; c < 8; c++)
                    acc[a][c] = fmaf(ar[a], br[c], acc[a][c]);
        }
        __syncthreads();
    }

    float4 sc_lo = *(const float4*)&scale[bn + tx * 8];
    float4 sc_hi = *(const float4*)&scale[bn + tx * 8 + 4];
    const float sc[8] = {sc_lo.x, sc_lo.y, sc_lo.z, sc_lo.w,
                         sc_hi.x, sc_hi.y, sc_hi.z, sc_hi.w};

#pragma unroll
    for (int a = 0; a < 8; a++) {
        const size_t rowoff = (size_t)(bm + ty * 8 + a) * Ddim + bn + tx * 8;
        float4 o0, o1;
        o0.x = acc[a][0] * sc[0]; o0.y = acc[a][1] * sc[1];
        o0.z = acc[a][2] * sc[2]; o0.w = acc[a][3] * sc[3];
        o1.x = acc[a][4] * sc[4]; o1.y = acc[a][5] * sc[5];
        o1.z = acc[a][6] * sc[6]; o1.w = acc[a][7] * sc[7];
        *(float4*)&out[rowoff]     = o0;
        *(float4*)&out[rowoff + 4] = o1;
    }
}

// ---------------------------------------------------------------------------
extern "C" void kernel_launch(void* const* d_in, const int* in_sizes, int n_in,
                              void* d_out, int out_size)
{
    const float* r     = (const float*)d_in[0];
    const float* w     = (const float*)d_in[1];
    const float* k     = (const float*)d_in[2];
    const float* v     = (const float*)d_in[3];
    const float* iclr  = (const float*)d_in[4];
    const int*   wq    = (const int*)d_in[5];
    const float* wsc   = (const float*)d_in[6];
    float* out = (float*)d_out;

    wkv7_pre_kernel<<<Bdim * Tdim * Hdim / 8, 256>>>(w, k, iclr);
    wkv7_scan_kernel<<<Bdim * Hdim, 256>>>(r, k, v);

    dim3 grid(Ddim / GBN, Mtot / GBM);
    dequant_gemm_kernel<<<grid, 256>>>(wq, wsc, out);
}

// round 5
// speedup vs baseline: 2.4450x; 1.7207x over previous
#include <cuda_runtime.h>
#include <cuda_bf16.h>
#include <math.h>
#include <stdint.h>

#define Bdim 4
#define Tdim 512
#define Hdim 32
#define Ndim 64
#define Ddim 2048           // Hdim*Ndim
#define Mtot (Bdim*Tdim)    // 2048
#define Ktot Ddim           // 2048

// ---------------- device scratch (no allocs allowed) ----------------
__device__ float          g_d [Bdim * Tdim * Ddim];   // decay
__device__ float          g_kk[Bdim * Tdim * Ddim];   // normalized k
__device__ float          g_bb[Bdim * Tdim * Ddim];   // kk * sigmoid(iclr)
__device__ __nv_bfloat16  g_Ahi[Mtot * Ktot];         // y hi (bf16)
__device__ __nv_bfloat16  g_Alo[Mtot * Ktot];         // y lo (bf16)
__device__ __nv_bfloat16  g_Wb [Ddim * Ktot];         // W (bf16, exact)

// ---------------- PTX helpers (plain sm_80+ features only) ----------------
__device__ __forceinline__ uint32_t smem_u32(const void* p) {
    return (uint32_t)__cvta_generic_to_shared(p);
}
__device__ __forceinline__ void cp_async16(uint32_t smaddr, const void* g) {
    asm volatile("cp.async.cg.shared.global [%0], [%1], 16;" :: "r"(smaddr), "l"(g));
}
#define CP_COMMIT() asm volatile("cp.async.commit_group;" ::: "memory")
#define CP_WAIT(n)  asm volatile("cp.async.wait_group %0;" :: "n"(n) : "memory")

__device__ __forceinline__ void ldsm_x4(uint32_t* r, uint32_t addr) {
    asm volatile("ldmatrix.sync.aligned.m8n8.x4.shared.b16 {%0,%1,%2,%3}, [%4];"
        : "=r"(r[0]), "=r"(r[1]), "=r"(r[2]), "=r"(r[3]) : "r"(addr));
}
__device__ __forceinline__ void mma_bf16(float* d, const uint32_t* a, const uint32_t* b) {
    asm volatile("mma.sync.aligned.m16n8k16.row.col.f32.bf16.bf16.f32 "
        "{%0,%1,%2,%3}, {%4,%5,%6,%7}, {%8,%9}, {%0,%1,%2,%3};"
        : "+f"(d[0]), "+f"(d[1]), "+f"(d[2]), "+f"(d[3])
        : "r"(a[0]), "r"(a[1]), "r"(a[2]), "r"(a[3]), "r"(b[0]), "r"(b[1]));
}

// ---------------------------------------------------------------------------
// Kernel 0a: elementwise precompute (decay, kk, b)
// ---------------------------------------------------------------------------
__global__ void __launch_bounds__(256) wkv7_pre_kernel(
    const float* __restrict__ w, const float* __restrict__ k,
    const float* __restrict__ iclr)
{
    const int vec  = blockIdx.x * 8 + (threadIdx.x >> 5);
    const int lane = threadIdx.x & 31;
    const size_t base = (size_t)vec * Ndim;

    float k0 = k[base + lane], k1 = k[base + lane + 32];
    float p = fmaf(k0, k0, k1 * k1);
#pragma unroll
    for (int o = 16; o; o >>= 1) p += __shfl_xor_sync(0xffffffffu, p, o);
    const float inv = rsqrtf(p + 1e-12f);

    float w0 = w[base + lane], w1 = w[base + lane + 32];
    float c0 = iclr[base + lane], c1 = iclr[base + lane + 32];

    g_d[base + lane]      = __expf(-__expf(w0));
    g_d[base + lane + 32] = __expf(-__expf(w1));
    const float kk0 = k0 * inv, kk1 = k1 * inv;
    g_kk[base + lane]      = kk0;
    g_kk[base + lane + 32] = kk1;
    g_bb[base + lane]      = kk0 / (1.0f + __expf(-c0));
    g_bb[base + lane + 32] = kk1 / (1.0f + __expf(-c1));
}

// ---------------------------------------------------------------------------
// Kernel 0b: Wq (int32) -> bf16 (exact, |v|<=128)
// ---------------------------------------------------------------------------
__global__ void __launch_bounds__(256) wconv_kernel(const int* __restrict__ wq)
{
    const size_t i4 = (size_t)blockIdx.x * 256 + threadIdx.x;   // int4 index
    int4 q = ((const int4*)wq)[i4];
    __nv_bfloat16 o[4];
    o[0] = __float2bfloat16((float)q.x);
    o[1] = __float2bfloat16((float)q.y);
    o[2] = __float2bfloat16((float)q.z);
    o[3] = __float2bfloat16((float)q.w);
    *(uint2*)&g_Wb[i4 * 4] = *(uint2*)o;
}

// ---------------------------------------------------------------------------
// Kernel 1: WKV scan with cp.async ring (depth 8, prefetch distance 7).
// One block (256 thr) per (b,h). row=tid>>2, seg=tid&3, 16 fp32 state regs.
// Writes y as bf16 hi/lo.
// ---------------------------------------------------------------------------
__global__ void __launch_bounds__(256) wkv7_scan_kernel(
    const float* __restrict__ r, const float* __restrict__ k,
    const float* __restrict__ v)
{
    const int bh = blockIdx.x;
    const int b  = bh >> 5;
    const int h  = bh & 31;
    const int tid = threadIdx.x;
    const int row = tid >> 2;
    const int seg = tid & 3;
    const int jb  = seg * 16;

    // ring: 8 step-slots; per slot: d[0,64) kk[64,128) b[128,192) k[192,256) r[256,320) v[320,384)
    __shared__ __align__(16) float sbuf[8][6 * Ndim];

    float state[16];
#pragma unroll
    for (int c = 0; c < 16; c++) state[c] = 0.f;

    const int lvec = tid >> 4;          // 0..5
    const int lq   = tid & 15;          // 0..15
    const size_t vstep = (size_t)Hdim * Ndim / 4;

    const float4* gsrc = nullptr;
    if (tid < 96) {
        const float* sp;
        switch (lvec) {
            case 0: sp = g_d;  break;
            case 1: sp = g_kk; break;
            case 2: sp = g_bb; break;
            case 3: sp = k;    break;
            case 4: sp = r;    break;
            default: sp = v;   break;
        }
        gsrc = (const float4*)sp + (((size_t)b * Tdim) * Hdim + h) * (Ndim / 4) + lq;
#pragma unroll
        for (int s = 0; s < 7; s++) {
            cp_async16(smem_u32(&sbuf[s][0]) + tid * 16, gsrc + (size_t)s * vstep);
            CP_COMMIT();
        }
        gsrc += 7 * vstep;
    }

    size_t ybase = ((size_t)b * Tdim) * Ddim + h * Ndim + row;

    for (int t = 0; t < Tdim; t++) {
        if (tid < 96) CP_WAIT(6);
        __syncthreads();

        if (tid < 96) {
            if (t + 7 < Tdim)
                cp_async16(smem_u32(&sbuf[(t + 7) & 7][0]) + tid * 16, gsrc);
            CP_COMMIT();
            gsrc += vstep;
        }

        const float* s = sbuf[t & 7];
        const float4* d4  = (const float4*)(s +   0 + jb);
        const float4* kk4 = (const float4*)(s +  64 + jb);
        const float4* b4  = (const float4*)(s + 128 + jb);
        const float4* k4  = (const float4*)(s + 192 + jb);
        const float4* r4  = (const float4*)(s + 256 + jb);
        const float vv = s[320 + row];

        float p0 = 0.f, p1 = 0.f, p2 = 0.f, p3 = 0.f;
#pragma unroll
        for (int q = 0; q < 4; q++) {
            float4 kv = kk4[q];
            p0 = fmaf(state[4*q+0], kv.x, p0);
            p1 = fmaf(state[4*q+1], kv.y, p1);
            p2 = fmaf(state[4*q+2], kv.z, p2);
            p3 = fmaf(state[4*q+3], kv.w, p3);
        }
        float sa_p = (p0 + p1) + (p2 + p3);
        sa_p += __shfl_xor_sync(0xffffffffu, sa_p, 1);
        sa_p += __shfl_xor_sync(0xffffffffu, sa_p, 2);
        const float sa = -sa_p;

        float y0 = 0.f, y1 = 0.f, y2 = 0.f, y3 = 0.f;
#pragma unroll
        for (int q = 0; q < 4; q++) {
            float4 dd = d4[q], bb = b4[q], kq = k4[q], rr = r4[q];
            float t0 = fmaf(sa, bb.x, vv * kq.x);
            float t1 = fmaf(sa, bb.y, vv * kq.y);
            float t2 = fmaf(sa, bb.z, vv * kq.z);
            float t3 = fmaf(sa, bb.w, vv * kq.w);
            state[4*q+0] = fmaf(state[4*q+0], dd.x, t0);
            state[4*q+1] = fmaf(state[4*q+1], dd.y, t1);
            state[4*q+2] = fmaf(state[4*q+2], dd.z, t2);
            state[4*q+3] = fmaf(state[4*q+3], dd.w, t3);
            y0 = fmaf(state[4*q+0], rr.x, y0);
            y1 = fmaf(state[4*q+1], rr.y, y1);
            y2 = fmaf(state[4*q+2], rr.z, y2);
            y3 = fmaf(state[4*q+3], rr.w, y3);
        }
        float yp = (y0 + y1) + (y2 + y3);
        yp += __shfl_xor_sync(0xffffffffu, yp, 1);
        yp += __shfl_xor_sync(0xffffffffu, yp, 2);
        if (seg == 0) {
            const size_t yi = ybase + (size_t)t * Ddim;
            __nv_bfloat16 hi = __float2bfloat16(yp);
            g_Ahi[yi] = hi;
            g_Alo[yi] = __float2bfloat16(yp - __bfloat162float(hi));
        }
    }
}

// ---------------------------------------------------------------------------
// Kernel 2: mma.sync bf16 split GEMM (NT).
// CTA: 128x128 tile, BK=64. 8 warps (2x4), warp tile 64x32.
// smem: SW128-swizzled bf16 tiles (Ahi, Alo, W), double-buffered cp.async.
// out[m,o] = scale[o] * (Ahi[m,:]+Alo[m,:]) . Wb[o,:]
// ---------------------------------------------------------------------------
#define NCH   (Ktot / 64)          // 32 K-chunks
#define STAGE 49152                // 3 tiles * 16KB
#define GSM_TOTAL (2 * STAGE)

__device__ __forceinline__ uint32_t swz(uint32_t row, uint32_t cbyte) {
    uint32_t off = row * 128 + cbyte;
    return off ^ ((off >> 3) & 0x70);
}

__global__ void __launch_bounds__(256) mma_gemm_kernel(
    const float* __restrict__ scale, float* __restrict__ out)
{
    extern __shared__ __align__(1024) char smem[];
    const uint32_t sb = smem_u32(smem);
    const int tid  = threadIdx.x;
    const int wid  = tid >> 5;
    const int lane = tid & 31;
    const int bm = blockIdx.y * 128;
    const int bn = blockIdx.x * 128;

    const int mbase = (wid >> 2) * 64;      // 0 / 64
    const int nbase = (wid & 3) * 32;       // 0/32/64/96

    // ---- async stage loader: 3072 16B vectors / 256 thr = 12 each ----
    auto load_stage = [&](int c, int p) {
        const uint32_t base = sb + p * STAGE;
        const size_t kof = (size_t)c * 64;
#pragma unroll
        for (int it = 0; it < 12; it++) {
            const int id   = tid + it * 256;        // 0..3071
            const int tile = id >> 10;              // 0:Ahi 1:Alo 2:W
            const int rem  = id & 1023;
            const int rw   = rem >> 3;              // row 0..127
            const int c8   = rem & 7;               // 16B chunk
            const uint32_t sa = base + tile * 16384 + swz(rw, c8 * 16);
            const __nv_bfloat16* g =
                (tile == 0) ? g_Ahi + (size_t)(bm + rw) * Ktot + kof + c8 * 8 :
                (tile == 1) ? g_Alo + (size_t)(bm + rw) * Ktot + kof + c8 * 8 :
                              g_Wb  + (size_t)(bn + rw) * Ktot + kof + c8 * 8;
            cp_async16(sa, g);
        }
    };

    float acc[4][4][4];
#pragma unroll
    for (int i = 0; i < 4; i++)
#pragma unroll
        for (int j = 0; j < 4; j++)
#pragma unroll
            for (int q = 0; q < 4; q++) acc[i][j][q] = 0.f;

    // per-lane ldmatrix address components
    const uint32_t rowAl = lane & 15;               // A: row within m16 tile
    const uint32_t cexA  = (lane >> 4) * 16;        // A: +16B for k8-15 tiles
    const uint32_t rowBl = ((lane >> 4) << 3) + (lane & 7);   // B: n within 16
    const uint32_t cexB  = ((lane >> 3) & 1) * 16;  // B: +16B for k8-15 tiles

    load_stage(0, 0);
    CP_COMMIT();

    for (int c = 0; c < NCH; c++) {
        const int p = c & 1;
        if (c + 1 < NCH) {
            load_stage(c + 1, p ^ 1);
            CP_COMMIT();
            CP_WAIT(1);
        } else {
            CP_WAIT(0);
        }
        __syncthreads();

        const uint32_t aB = sb + p * STAGE;         // Ahi
        const uint32_t lB = aB + 16384;              // Alo
        const uint32_t wB = aB + 32768;              // W

#pragma unroll
        for (int ks = 0; ks < 4; ks++) {
            const uint32_t kca = ks * 32 + cexA;
            const uint32_t kcb = ks * 32 + cexB;
            uint32_t bq[4][2];
            {   // B: two x4 loads cover n 0..31 of this warp
                uint32_t t[4];
                ldsm_x4(t, wB + swz(nbase + rowBl, kcb));
                bq[0][0] = t[0]; bq[0][1] = t[1]; bq[1][0] = t[2]; bq[1][1] = t[3];
                ldsm_x4(t, wB + swz(nbase + 16 + rowBl, kcb));
                bq[2][0] = t[0]; bq[2][1] = t[1]; bq[3][0] = t[2]; bq[3][1] = t[3];
            }
            uint32_t ah[4][4], al[4][4];
#pragma unroll
            for (int im = 0; im < 4; im++) {
                ldsm_x4(ah[im], aB + swz(mbase + im * 16 + rowAl, kca));
                ldsm_x4(al[im], lB + swz(mbase + im * 16 + rowAl, kca));
            }
#pragma unroll
            for (int im = 0; im < 4; im++)
#pragma unroll
                for (int in = 0; in < 4; in++) {
                    mma_bf16(acc[im][in], ah[im], bq[in]);
                    mma_bf16(acc[im][in], al[im], bq[in]);
                }
        }
        __syncthreads();
    }

    // ---- epilogue: scale by scale[col], store float2 from fragments ----
    const int gid = lane >> 2;     // 0..7 (row within 8)
    const int tig = lane & 3;      // 0..3 (col pair)
#pragma unroll
    for (int in = 0; in < 4; in++) {
        const int col = bn + nbase + in * 8 + tig * 2;
        const float s0 = scale[col], s1 = scale[col + 1];
#pragma unroll
        for (int im = 0; im < 4; im++) {
            const int row0 = bm + mbase + im * 16 + gid;
            float2 o0, o1;
            o0.x = acc[im][in][0] * s0; o0.y = acc[im][in][1] * s1;
            o1.x = acc[im][in][2] * s0; o1.y = acc[im][in][3] * s1;
            *(float2*)&out[(size_t)row0 * Ddim + col]       = o0;
            *(float2*)&out[(size_t)(row0 + 8) * Ddim + col] = o1;
        }
    }
}

// ---------------------------------------------------------------------------
extern "C" void kernel_launch(void* const* d_in, const int* in_sizes, int n_in,
                              void* d_out, int out_size)
{
    const float* r     = (const float*)d_in[0];
    const float* w     = (const float*)d_in[1];
    const float* k     = (const float*)d_in[2];
    const float* v     = (const float*)d_in[3];
    const float* iclr  = (const float*)d_in[4];
    const int*   wq    = (const int*)d_in[5];
    const float* wsc   = (const float*)d_in[6];
    float* out = (float*)d_out;

    wkv7_pre_kernel<<<Bdim * Tdim * Hdim / 8, 256>>>(w, k, iclr);
    wconv_kernel<<<(Ddim * Ktot) / 1024, 256>>>(wq);
    wkv7_scan_kernel<<<Bdim * Hdim, 256>>>(r, k, v);

    static int smem_set = 0;
    if (!smem_set) {
        cudaFuncSetAttribute(mma_gemm_kernel,
                             cudaFuncAttributeMaxDynamicSharedMemorySize, GSM_TOTAL);
        smem_set = 1;
    }
    dim3 grid(Ddim / 128, Mtot / 128);
    mma_gemm_kernel<<<grid, 256, GSM_TOTAL>>>(wsc, out);
}

// round 6
// speedup vs baseline: 2.6089x; 1.0671x over previous
#include <cuda_runtime.h>
#include <cuda_bf16.h>
#include <math.h>
#include <stdint.h>

#define Bdim 4
#define Tdim 512
#define Hdim 32
#define Ndim 64
#define Ddim 2048           // Hdim*Ndim
#define Mtot (Bdim*Tdim)    // 2048
#define Ktot Ddim           // 2048

// ---------------- device scratch (no allocs allowed) ----------------
__device__ float          g_d [Bdim * Tdim * Ddim];   // decay
__device__ float          g_kk[Bdim * Tdim * Ddim];   // normalized k
__device__ float          g_bb[Bdim * Tdim * Ddim];   // kk * sigmoid(iclr)
__device__ __nv_bfloat16  g_Ahi[Mtot * Ktot];         // y hi (bf16)
__device__ __nv_bfloat16  g_Alo[Mtot * Ktot];         // y lo (bf16)
__device__ __nv_bfloat16  g_Wb [Ddim * Ktot];         // W (bf16, exact)

// ---------------- PTX helpers (plain sm_80+ features only) ----------------
__device__ __forceinline__ uint32_t smem_u32(const void* p) {
    return (uint32_t)__cvta_generic_to_shared(p);
}
__device__ __forceinline__ void cp_async16(uint32_t smaddr, const void* g) {
    asm volatile("cp.async.cg.shared.global [%0], [%1], 16;" :: "r"(smaddr), "l"(g));
}
#define CP_COMMIT() asm volatile("cp.async.commit_group;" ::: "memory")
#define CP_WAIT(n)  asm volatile("cp.async.wait_group %0;" :: "n"(n) : "memory")

__device__ __forceinline__ void ldsm_x4(uint32_t* r, uint32_t addr) {
    asm volatile("ldmatrix.sync.aligned.m8n8.x4.shared.b16 {%0,%1,%2,%3}, [%4];"
        : "=r"(r[0]), "=r"(r[1]), "=r"(r[2]), "=r"(r[3]) : "r"(addr));
}
__device__ __forceinline__ void mma_bf16(float* d, const uint32_t* a, const uint32_t* b) {
    asm volatile("mma.sync.aligned.m16n8k16.row.col.f32.bf16.bf16.f32 "
        "{%0,%1,%2,%3}, {%4,%5,%6,%7}, {%8,%9}, {%0,%1,%2,%3};"
        : "+f"(d[0]), "+f"(d[1]), "+f"(d[2]), "+f"(d[3])
        : "r"(a[0]), "r"(a[1]), "r"(a[2]), "r"(a[3]), "r"(b[0]), "r"(b[1]));
}

// ---------------------------------------------------------------------------
// Kernel 0a: elementwise precompute (decay, kk, b)
// ---------------------------------------------------------------------------
__global__ void __launch_bounds__(256) wkv7_pre_kernel(
    const float* __restrict__ w, const float* __restrict__ k,
    const float* __restrict__ iclr)
{
    const int vec  = blockIdx.x * 8 + (threadIdx.x >> 5);
    const int lane = threadIdx.x & 31;
    const size_t base = (size_t)vec * Ndim;

    float k0 = k[base + lane], k1 = k[base + lane + 32];
    float p = fmaf(k0, k0, k1 * k1);
#pragma unroll
    for (int o = 16; o; o >>= 1) p += __shfl_xor_sync(0xffffffffu, p, o);
    const float inv = rsqrtf(p + 1e-12f);

    float w0 = w[base + lane], w1 = w[base + lane + 32];
    float c0 = iclr[base + lane], c1 = iclr[base + lane + 32];

    g_d[base + lane]      = __expf(-__expf(w0));
    g_d[base + lane + 32] = __expf(-__expf(w1));
    const float kk0 = k0 * inv, kk1 = k1 * inv;
    g_kk[base + lane]      = kk0;
    g_kk[base + lane + 32] = kk1;
    g_bb[base + lane]      = kk0 / (1.0f + __expf(-c0));
    g_bb[base + lane + 32] = kk1 / (1.0f + __expf(-c1));
}

// ---------------------------------------------------------------------------
// Kernel 0b: Wq (int32) -> bf16 (exact, |v|<=128)
// ---------------------------------------------------------------------------
__global__ void __launch_bounds__(256) wconv_kernel(const int* __restrict__ wq)
{
    const size_t i4 = (size_t)blockIdx.x * 256 + threadIdx.x;   // int4 index
    int4 q = ((const int4*)wq)[i4];
    __nv_bfloat16 o[4];
    o[0] = __float2bfloat16((float)q.x);
    o[1] = __float2bfloat16((float)q.y);
    o[2] = __float2bfloat16((float)q.z);
    o[3] = __float2bfloat16((float)q.w);
    *(uint2*)&g_Wb[i4 * 4] = *(uint2*)o;
}

// ---------------------------------------------------------------------------
// Kernel 1: WKV scan. 16-slot cp.async ring, ONE barrier per 4 steps.
// One block (256 thr) per (b,h). row=tid>>2, seg=tid&3, 16 fp32 state regs.
// Writes y as bf16 hi/lo.
// ---------------------------------------------------------------------------
__global__ void __launch_bounds__(256) wkv7_scan_kernel(
    const float* __restrict__ r, const float* __restrict__ k,
    const float* __restrict__ v)
{
    const int bh = blockIdx.x;
    const int b  = bh >> 5;
    const int h  = bh & 31;
    const int tid = threadIdx.x;
    const int row = tid >> 2;
    const int seg = tid & 3;
    const int jb  = seg * 16;

    // ring: 16 step-slots; per slot: d[0,64) kk[64,128) b[128,192) k[192,256) r[256,320) v[320,384)
    __shared__ __align__(16) float sbuf[16][6 * Ndim];

    float state[16];
#pragma unroll
    for (int c = 0; c < 16; c++) state[c] = 0.f;

    const int lvec = tid >> 4;          // 0..5
    const size_t vstep = (size_t)Hdim * Ndim / 4;

    const float4* gsrc = nullptr;
    if (tid < 96) {
        const int lq = tid & 15;
        const float* sp;
        switch (lvec) {
            case 0: sp = g_d;  break;
            case 1: sp = g_kk; break;
            case 2: sp = g_bb; break;
            case 3: sp = k;    break;
            case 4: sp = r;    break;
            default: sp = v;   break;
        }
        gsrc = (const float4*)sp + (((size_t)b * Tdim) * Hdim + h) * (Ndim / 4) + lq;
        // prologue: issue steps 0..7
#pragma unroll
        for (int s = 0; s < 8; s++) {
            cp_async16(smem_u32(&sbuf[s][0]) + tid * 16, gsrc + (size_t)s * vstep);
            CP_COMMIT();
        }
        gsrc += 8 * vstep;
    }

    size_t ybase = ((size_t)b * Tdim) * Ddim + h * Ndim + row;

    for (int t0 = 0; t0 < Tdim; t0 += 4) {
        if (tid < 96) CP_WAIT(4);       // steps t0..t0+3 landed
        __syncthreads();                 // publish to all warps

        // issue steps t0+8 .. t0+11
        if (tid < 96) {
#pragma unroll
            for (int u = 0; u < 4; u++) {
                const int ts = t0 + 8 + u;
                if (ts < Tdim)
                    cp_async16(smem_u32(&sbuf[ts & 15][0]) + tid * 16, gsrc);
                CP_COMMIT();
                gsrc += vstep;
            }
        }

        // 4 compute steps, no barriers between them
#pragma unroll
        for (int u = 0; u < 4; u++) {
            const int t = t0 + u;
            const float* s = sbuf[t & 15];
            const float4* d4  = (const float4*)(s +   0 + jb);
            const float4* kk4 = (const float4*)(s +  64 + jb);
            const float4* b4  = (const float4*)(s + 128 + jb);
            const float4* k4  = (const float4*)(s + 192 + jb);
            const float4* r4  = (const float4*)(s + 256 + jb);
            const float vv = s[320 + row];

            float p0 = 0.f, p1 = 0.f, p2 = 0.f, p3 = 0.f;
#pragma unroll
            for (int q = 0; q < 4; q++) {
                float4 kv = kk4[q];
                p0 = fmaf(state[4*q+0], kv.x, p0);
                p1 = fmaf(state[4*q+1], kv.y, p1);
                p2 = fmaf(state[4*q+2], kv.z, p2);
                p3 = fmaf(state[4*q+3], kv.w, p3);
            }
            float sa_p = (p0 + p1) + (p2 + p3);
            sa_p += __shfl_xor_sync(0xffffffffu, sa_p, 1);
            sa_p += __shfl_xor_sync(0xffffffffu, sa_p, 2);
            const float sa = -sa_p;

            float y0 = 0.f, y1 = 0.f, y2 = 0.f, y3 = 0.f;
#pragma unroll
            for (int q = 0; q < 4; q++) {
                float4 dd = d4[q], bb = b4[q], kq = k4[q], rr = r4[q];
                float t0f = fmaf(sa, bb.x, vv * kq.x);
                float t1f = fmaf(sa, bb.y, vv * kq.y);
                float t2f = fmaf(sa, bb.z, vv * kq.z);
                float t3f = fmaf(sa, bb.w, vv * kq.w);
                state[4*q+0] = fmaf(state[4*q+0], dd.x, t0f);
                state[4*q+1] = fmaf(state[4*q+1], dd.y, t1f);
                state[4*q+2] = fmaf(state[4*q+2], dd.z, t2f);
                state[4*q+3] = fmaf(state[4*q+3], dd.w, t3f);
                y0 = fmaf(state[4*q+0], rr.x, y0);
                y1 = fmaf(state[4*q+1], rr.y, y1);
                y2 = fmaf(state[4*q+2], rr.z, y2);
                y3 = fmaf(state[4*q+3], rr.w, y3);
            }
            float yp = (y0 + y1) + (y2 + y3);
            yp += __shfl_xor_sync(0xffffffffu, yp, 1);
            yp += __shfl_xor_sync(0xffffffffu, yp, 2);
            if (seg == 0) {
                const size_t yi = ybase + (size_t)t * Ddim;
                __nv_bfloat16 hi = __float2bfloat16(yp);
                g_Ahi[yi] = hi;
                g_Alo[yi] = __float2bfloat16(yp - __bfloat162float(hi));
            }
        }
    }
}

// ---------------------------------------------------------------------------
// Kernel 2: mma.sync bf16 split GEMM (NT). 128x128 tile, BK=64, 8 warps,
// SW128-swizzled smem, 3-stage cp.async pipeline, 1 barrier per chunk.
// out[m,o] = scale[o] * (Ahi[m,:]+Alo[m,:]) . Wb[o,:]
// ---------------------------------------------------------------------------
#define NCH   (Ktot / 64)          // 32 K-chunks
#define STAGE 49152                // 3 tiles * 16KB
#define GSM_TOTAL (3 * STAGE)

__device__ __forceinline__ uint32_t swz(uint32_t row, uint32_t cbyte) {
    uint32_t off = row * 128 + cbyte;
    return off ^ ((off >> 3) & 0x70);
}

__global__ void __launch_bounds__(256) mma_gemm_kernel(
    const float* __restrict__ scale, float* __restrict__ out)
{
    extern __shared__ __align__(1024) char smem[];
    const uint32_t sb = smem_u32(smem);
    const int tid  = threadIdx.x;
    const int wid  = tid >> 5;
    const int lane = tid & 31;
    const int bm = blockIdx.y * 128;
    const int bn = blockIdx.x * 128;

    const int mbase = (wid >> 2) * 64;      // 0 / 64
    const int nbase = (wid & 3) * 32;       // 0/32/64/96

    auto load_stage = [&](int c, int p) {
        const uint32_t base = sb + p * STAGE;
        const size_t kof = (size_t)c * 64;
#pragma unroll
        for (int it = 0; it < 12; it++) {
            const int id   = tid + it * 256;        // 0..3071
            const int tile = id >> 10;              // 0:Ahi 1:Alo 2:W
            const int rem  = id & 1023;
            const int rw   = rem >> 3;              // row 0..127
            const int c8   = rem & 7;               // 16B chunk
            const uint32_t sa = base + tile * 16384 + swz(rw, c8 * 16);
            const __nv_bfloat16* g =
                (tile == 0) ? g_Ahi + (size_t)(bm + rw) * Ktot + kof + c8 * 8 :
                (tile == 1) ? g_Alo + (size_t)(bm + rw) * Ktot + kof + c8 * 8 :
                              g_Wb  + (size_t)(bn + rw) * Ktot + kof + c8 * 8;
            cp_async16(sa, g);
        }
    };

    float acc[4][4][4];
#pragma unroll
    for (int i = 0; i < 4; i++)
#pragma unroll
        for (int j = 0; j < 4; j++)
#pragma unroll
            for (int q = 0; q < 4; q++) acc[i][j][q] = 0.f;

    const uint32_t rowAl = lane & 15;
    const uint32_t cexA  = (lane >> 4) * 16;
    const uint32_t rowBl = ((lane >> 4) << 3) + (lane & 7);
    const uint32_t cexB  = ((lane >> 3) & 1) * 16;

    load_stage(0, 0); CP_COMMIT();
    load_stage(1, 1); CP_COMMIT();

    for (int c = 0; c < NCH; c++) {
        const int p = c % 3;
        CP_WAIT(1);                 // stage c landed
        __syncthreads();
        if (c + 2 < NCH) load_stage(c + 2, (c + 2) % 3);
        CP_COMMIT();

        const uint32_t aB = sb + p * STAGE;          // Ahi
        const uint32_t lB = aB + 16384;               // Alo
        const uint32_t wB = aB + 32768;               // W

#pragma unroll
        for (int ks = 0; ks < 4; ks++) {
            const uint32_t kca = ks * 32 + cexA;
            const uint32_t kcb = ks * 32 + cexB;
            uint32_t bq[4][2];
            {
                uint32_t t[4];
                ldsm_x4(t, wB + swz(nbase + rowBl, kcb));
                bq[0][0] = t[0]; bq[0][1] = t[1]; bq[1][0] = t[2]; bq[1][1] = t[3];
                ldsm_x4(t, wB + swz(nbase + 16 + rowBl, kcb));
                bq[2][0] = t[0]; bq[2][1] = t[1]; bq[3][0] = t[2]; bq[3][1] = t[3];
            }
            uint32_t ah[4][4], al[4][4];
#pragma unroll
            for (int im = 0; im < 4; im++) {
                ldsm_x4(ah[im], aB + swz(mbase + im * 16 + rowAl, kca));
                ldsm_x4(al[im], lB + swz(mbase + im * 16 + rowAl, kca));
            }
#pragma unroll
            for (int im = 0; im < 4; im++)
#pragma unroll
                for (int in = 0; in < 4; in++) {
                    mma_bf16(acc[im][in], ah[im], bq[in]);
                    mma_bf16(acc[im][in], al[im], bq[in]);
                }
        }
    }

    // ---- epilogue ----
    const int gid = lane >> 2;
    const int tig = lane & 3;
#pragma unroll
    for (int in = 0; in < 4; in++) {
        const int col = bn + nbase + in * 8 + tig * 2;
        const float s0 = scale[col], s1 = scale[col + 1];
#pragma unroll
        for (int im = 0; im < 4; im++) {
            const int row0 = bm + mbase + im * 16 + gid;
            float2 o0, o1;
            o0.x = acc[im][in][0] * s0; o0.y = acc[im][in][1] * s1;
            o1.x = acc[im][in][2] * s0; o1.y = acc[im][in][3] * s1;
            *(float2*)&out[(size_t)row0 * Ddim + col]       = o0;
            *(float2*)&out[(size_t)(row0 + 8) * Ddim + col] = o1;
        }
    }
}

// ---------------------------------------------------------------------------
extern "C" void kernel_launch(void* const* d_in, const int* in_sizes, int n_in,
                              void* d_out, int out_size)
{
    const float* r     = (const float*)d_in[0];
    const float* w     = (const float*)d_in[1];
    const float* k     = (const float*)d_in[2];
    const float* v     = (const float*)d_in[3];
    const float* iclr  = (const float*)d_in[4];
    const int*   wq    = (const int*)d_in[5];
    const float* wsc   = (const float*)d_in[6];
    float* out = (float*)d_out;

    wkv7_pre_kernel<<<Bdim * Tdim * Hdim / 8, 256>>>(w, k, iclr);
    wconv_kernel<<<(Ddim * Ktot) / 1024, 256>>>(wq);
    wkv7_scan_kernel<<<Bdim * Hdim, 256>>>(r, k, v);

    static int smem_set = 0;
    if (!smem_set) {
        cudaFuncSetAttribute(mma_gemm_kernel,
                             cudaFuncAttributeMaxDynamicSharedMemorySize, GSM_TOTAL);
        smem_set = 1;
    }
    dim3 grid(Ddim / 128, Mtot / 128);
    mma_gemm_kernel<<<grid, 256, GSM_TOTAL>>>(wsc, out);
}